// round 13
// baseline (speedup 1.0000x reference)
#include <cuda_runtime.h>
#include <cuda_fp16.h>
#include <math.h>
#include <stdint.h>

// ---------------- problem constants ----------------
#define BQ 16
#define TT 2048
#define ED 1024
#define AD 512
#define DD 1024
#define CD 64
#define KSY 2
#define CK 15
#define KW 31
#define MM (BQ*TT)
#define KK 1088            // ED + CD concatenated K

// ---------------- GEMM tiling: single col pass ----------------
#define BM 64
#define BN 512
#define BK 32
#define NKIT (KK/BK)       // 34
#define NENCKIT (ED/BK)    // 32
#define NTILES (MM/BM)     // 512
#define STAGE_BYTES 36864  // A 4K + B 32K
#define RED_BYTES 4096
#define SMEM_REQ (3*STAGE_BYTES + RED_BYTES)   // 114688
#define NTHREADS 512       // 16 warps: 1 (m) x 16 (n), warp tile 64x32
#define GRID_P 148

// ---------------- merged prep dispatch ----------------
#define CONV_BLKS (512*16)             // 8192
#define WS_BLKS AD                     // 512
#define DEC_BLKS 1024
#define INIT_BLKS 64
#define PREP_BLKS (CONV_BLKS + WS_BLKS + DEC_BLKS + INIT_BLKS)

// ---------------- scratch ----------------
__device__ __half g_Ahc[(size_t)MM*CD];   // conv features (fp16)
__device__ __half g_Bh[(size_t)AD*KK];
__device__ float  g_decproj[BQ*AD];
__device__ float  g_score[MM];

// ---------------- helpers ----------------
__device__ __forceinline__ uint32_t smem_u32(const void* p){
    uint32_t a;
    asm("{ .reg .u64 t; cvta.to.shared.u64 t, %1; cvt.u32.u64 %0, t; }" : "=r"(a) : "l"(p));
    return a;
}
__device__ __forceinline__ void cp16(uint32_t dst, const void* src){
    asm volatile("cp.async.cg.shared.global [%0], [%1], 16;" :: "r"(dst), "l"(src) : "memory");
}
// 64B rows, 16B granules, XOR swizzle for conflict-free ldmatrix
__device__ __forceinline__ uint32_t swz(uint32_t r, uint32_t g){
    return r * 64u + ((g ^ ((r >> 1) & 3u)) << 4);
}
#define MMA16816(d, a, b) \
    asm volatile("mma.sync.aligned.m16n8k16.row.col.f32.f16.f16.f32 " \
        "{%0,%1,%2,%3}, {%4,%5,%6,%7}, {%8,%9}, {%0,%1,%2,%3};" \
        : "+f"((d)[0]), "+f"((d)[1]), "+f"((d)[2]), "+f"((d)[3]) \
        : "r"((a)[0]), "r"((a)[1]), "r"((a)[2]), "r"((a)[3]), \
          "r"((b)[0]), "r"((b)[1]))

// ---------------- merged prep: conv | w_split | dec | init ----------------
__global__ void prep_kernel(const float* __restrict__ state,
                            const float* __restrict__ Wc,
                            const float* __restrict__ We,
                            const float* __restrict__ Wa,
                            const float* __restrict__ h,
                            const float* __restrict__ Wd,
                            const float* __restrict__ be,
                            float* __restrict__ cctx){
    __shared__ float sW[CD * KSY * KW];
    int bid = blockIdx.x;
    int tid = threadIdx.x;

    if (bid < CONV_BLKS){
        // ---- conv over time -> fp16 [MM, 64] ----
        for (int i = tid; i < CD * KSY * KW; i += 256) sW[i] = Wc[i];
        __syncthreads();

        int xb = bid & 511;
        int b  = bid >> 9;
        int c = tid & 63;
        int t = xb * 4 + (tid >> 6);

        const float* s0 = state + (b * KSY + 0) * TT;
        const float* s1 = state + (b * KSY + 1) * TT;
        const float* w0 = &sW[(c * KSY + 0) * KW];
        const float* w1 = &sW[(c * KSY + 1) * KW];

        float acc = 0.f;
#pragma unroll
        for (int hh = 0; hh < KW; ++hh){
            int tt = t + hh - CK;
            bool ok = (tt >= 0) && (tt < TT);
            float v0 = ok ? s0[tt] : 0.f;
            float v1 = ok ? s1[tt] : 0.f;
            acc = fmaf(v0, w0[hh], acc);
            acc = fmaf(v1, w1[hh], acc);
        }
        g_Ahc[(size_t)(b * TT + t) * CD + c] = __float2half_rn(acc);
    } else if (bid < CONV_BLKS + WS_BLKS){
        // ---- weights fp16, concatenated K ----
        int n = bid - CONV_BLKS;
        for (int k = tid; k < KK; k += 256){
            float x = (k < ED) ? We[(size_t)n * ED + k] : Wa[n * CD + (k - ED)];
            g_Bh[(size_t)n * KK + k] = __float2half_rn(x);
        }
    } else if (bid < CONV_BLKS + WS_BLKS + DEC_BLKS){
        // ---- decoder projection, warp-per-output ----
        int bb = bid - CONV_BLKS - WS_BLKS;
        int wgid = (bb * 256 + tid) >> 5;   // 0..8191
        int lane = tid & 31;
        int b = wgid >> 9;
        int a = wgid & (AD - 1);
        const float4* hv = (const float4*)(h + b * DD) + lane;
        const float4* wv = (const float4*)(Wd + (size_t)a * DD) + lane;
        float acc = 0.f;
#pragma unroll
        for (int k = 0; k < 8; ++k){
            float4 x = hv[k * 32], w = wv[k * 32];
            acc = fmaf(x.x, w.x, acc); acc = fmaf(x.y, w.y, acc);
            acc = fmaf(x.z, w.z, acc); acc = fmaf(x.w, w.w, acc);
        }
#pragma unroll
        for (int s = 16; s > 0; s >>= 1) acc += __shfl_xor_sync(~0u, acc, s);
        if (lane == 0) g_decproj[wgid] = acc + be[a];
    } else {
        // ---- zero context output ----
        int bb = bid - CONV_BLKS - WS_BLKS - DEC_BLKS;
        int i = bb * 256 + tid;
        if (i < BQ * ED) cctx[i] = 0.f;
    }
}

// ---------------- persistent fused GEMM, BN=512 single pass ----------------
__global__ void __launch_bounds__(NTHREADS, 1)
mma_kernel(const float* __restrict__ enc, const float* __restrict__ Wout,
           const float* __restrict__ b_out){
    extern __shared__ char smraw[];
    uint32_t sbase = smem_u32(smraw);
    float* red = reinterpret_cast<float*>(smraw + 3 * STAGE_BYTES);
    int tid = threadIdx.x;
    int lane = tid & 31;
    int wid = tid >> 5;          // warp_n 0..15 -> 32 cols each

    // A producer mapping (threads 0..255): thread -> (row, 16B granule)
    int rTA = tid >> 2, fqT = tid & 3;
    uint32_t stsOffA = swz((uint32_t)rTA, (uint32_t)fqT);

    // ldmatrix within-stage offsets
    uint32_t offA[4][2];
#pragma unroll
    for (int fm = 0; fm < 4; ++fm)
#pragma unroll
        for (int k16 = 0; k16 < 2; ++k16){
            uint32_t r = fm * 16 + (lane & 15);
            uint32_t g = k16 * 2 + (lane >> 4);
            offA[fm][k16] = swz(r, g);
        }
    uint32_t offB2[2][2];
#pragma unroll
    for (int fp = 0; fp < 2; ++fp)
#pragma unroll
        for (int k16 = 0; k16 < 2; ++k16){
            uint32_t r = wid * 32 + fp * 16 + (((lane >> 4) & 1) * 8) + (lane & 7);
            uint32_t g = k16 * 2 + ((lane >> 3) & 1);
            offB2[fp][k16] = swz(r, g) + 4096u;
        }

    for (int tile = blockIdx.x; tile < NTILES; tile += gridDim.x){
        int rowBase = tile * BM;
        const float* encRow = enc + (size_t)(rowBase + rTA) * ED + fqT * 8;

        __syncthreads();   // previous tile's stage/red reads all retired

        float acc[4][4][4];
#pragma unroll
        for (int fm = 0; fm < 4; ++fm)
#pragma unroll
            for (int fn = 0; fn < 4; ++fn)
#pragma unroll
                for (int q = 0; q < 4; ++q) acc[fm][fn][q] = 0.f;

        float4 av0, av1;
        auto ldgA = [&](int k0){
            av0 = *(const float4*)(encRow + k0);
            av1 = *(const float4*)(encRow + k0 + 4);
        };
        auto stsA = [&](uint32_t st){
            float xs[8] = {av0.x, av0.y, av0.z, av0.w, av1.x, av1.y, av1.z, av1.w};
            uint32_t hq[4];
#pragma unroll
            for (int j = 0; j < 4; ++j){
                __half2 hh = __halves2half2(__float2half_rn(xs[2*j]),
                                            __float2half_rn(xs[2*j+1]));
                hq[j] = *(uint32_t*)&hh;
            }
            asm volatile("st.shared.v4.b32 [%0], {%1,%2,%3,%4};"
                :: "r"(st + stsOffA), "r"(hq[0]), "r"(hq[1]), "r"(hq[2]), "r"(hq[3]) : "memory");
        };
        auto cpB = [&](uint32_t st, int k0){
#pragma unroll
            for (int j = 0; j < 4; ++j){
                int i = tid + j * 512;
                int r = i >> 2, g = i & 3;
                cp16(st + 4096u + swz(r, g),
                     g_Bh + (size_t)r * KK + k0 + g * 8);
            }
        };
        auto cpConvA = [&](uint32_t st, int c0){
            cp16(st + stsOffA, g_Ahc + (size_t)(rowBase + rTA) * CD + c0 + fqT * 8);
        };

        // ---- prologue ----
        if (tid < 256){ ldgA(0); stsA(sbase); }
        cpB(sbase, 0);
        asm volatile("cp.async.commit_group;" ::: "memory");
        if (tid < 256){ ldgA(32); stsA(sbase + STAGE_BYTES); }
        cpB(sbase + STAGE_BYTES, 32);
        asm volatile("cp.async.commit_group;" ::: "memory");
        if (tid < 256) ldgA(64);

        // ---- mainloop: MMA first, then produce stage it+2 ----
        for (int it = 0; it < NKIT; ++it){
            asm volatile("cp.async.wait_group 1;" ::: "memory");
            __syncthreads();

            uint32_t st = sbase + (uint32_t)(it % 3) * STAGE_BYTES;
#pragma unroll
            for (int k16 = 0; k16 < 2; ++k16){
                uint32_t b[4][2];
#pragma unroll
                for (int fp = 0; fp < 2; ++fp)
                    asm volatile("ldmatrix.sync.aligned.m8n8.x4.shared.b16 {%0,%1,%2,%3}, [%4];"
                        : "=r"(b[2*fp][0]), "=r"(b[2*fp][1]), "=r"(b[2*fp+1][0]), "=r"(b[2*fp+1][1])
                        : "r"(st + offB2[fp][k16]));
                uint32_t a[4][4];
#pragma unroll
                for (int fm = 0; fm < 4; ++fm)
                    asm volatile("ldmatrix.sync.aligned.m8n8.x4.shared.b16 {%0,%1,%2,%3}, [%4];"
                        : "=r"(a[fm][0]), "=r"(a[fm][1]), "=r"(a[fm][2]), "=r"(a[fm][3])
                        : "r"(st + offA[fm][k16]));
#pragma unroll
                for (int fm = 0; fm < 4; ++fm)
#pragma unroll
                    for (int fn = 0; fn < 4; ++fn)
                        MMA16816(acc[fm][fn], a[fm], b[fn]);
            }

            // ---- produce stage it+2 while tensor pipe drains ----
            int nk = it + 2;
            uint32_t stn = sbase + (uint32_t)(nk % 3) * STAGE_BYTES;
            if (nk < NENCKIT){
                if (tid < 256) stsA(stn);
                cpB(stn, nk * BK);
                if (tid < 256 && nk + 1 < NENCKIT) ldgA((nk + 1) * BK);
            } else if (nk < NKIT){
                if (tid < 256) cpConvA(stn, (nk - NENCKIT) * BK);
                cpB(stn, nk * BK);
            }
            asm volatile("cp.async.commit_group;" ::: "memory");
        }

        // ---- epilogue: +decproj, tanh, dot W_out, cross-warp reduce, store ----
        int b = rowBase >> 11;
        float wo[4][2], dp[4][2];
#pragma unroll
        for (int fn = 0; fn < 4; ++fn){
            int c0 = wid * 32 + fn * 8 + 2 * (lane & 3);
            wo[fn][0] = Wout[c0];               wo[fn][1] = Wout[c0 + 1];
            dp[fn][0] = g_decproj[b * AD + c0]; dp[fn][1] = g_decproj[b * AD + c0 + 1];
        }
        int g = lane >> 2;
#pragma unroll
        for (int fm = 0; fm < 4; ++fm){
            float s0 = 0.f, s1 = 0.f;
#pragma unroll
            for (int fn = 0; fn < 4; ++fn){
                s0 += tanhf(acc[fm][fn][0] + dp[fn][0]) * wo[fn][0];
                s0 += tanhf(acc[fm][fn][1] + dp[fn][1]) * wo[fn][1];
                s1 += tanhf(acc[fm][fn][2] + dp[fn][0]) * wo[fn][0];
                s1 += tanhf(acc[fm][fn][3] + dp[fn][1]) * wo[fn][1];
            }
            s0 += __shfl_xor_sync(~0u, s0, 1); s0 += __shfl_xor_sync(~0u, s0, 2);
            s1 += __shfl_xor_sync(~0u, s1, 1); s1 += __shfl_xor_sync(~0u, s1, 2);
            if ((lane & 3) == 0){
                red[(fm * 16 + g) * 16 + wid]     = s0;
                red[(fm * 16 + 8 + g) * 16 + wid] = s1;
            }
        }
        __syncthreads();
        if (tid < BM){
            float s = 0.f;
#pragma unroll
            for (int j = 0; j < 16; ++j) s += red[tid * 16 + j];
            g_score[rowBase + tid] = s + b_out[0];
        }
    }
}

// ---------------- softmax over T per batch ----------------
__global__ void softmax_kernel(const unsigned char* __restrict__ mask,
                               float* __restrict__ wout){
    __shared__ float red[256];
    int b = blockIdx.x;
    int tid = threadIdx.x;

    float local[8];
    float mx = -INFINITY;
#pragma unroll
    for (int i = 0; i < 8; ++i){
        int t = i * 256 + tid;
        float v = g_score[b * TT + t];
        if (mask[b * TT + t]) v = -INFINITY;
        local[i] = v;
        mx = fmaxf(mx, v);
    }
    red[tid] = mx; __syncthreads();
    for (int s = 128; s > 0; s >>= 1){
        if (tid < s) red[tid] = fmaxf(red[tid], red[tid + s]);
        __syncthreads();
    }
    mx = red[0]; __syncthreads();

    float sum = 0.f;
#pragma unroll
    for (int i = 0; i < 8; ++i){
        local[i] = expf(2.f * (local[i] - mx));
        sum += local[i];
    }
    red[tid] = sum; __syncthreads();
    for (int s = 128; s > 0; s >>= 1){
        if (tid < s) red[tid] += red[tid + s];
        __syncthreads();
    }
    float inv = 1.f / red[0];
#pragma unroll
    for (int i = 0; i < 8; ++i)
        wout[b * TT + i * 256 + tid] = local[i] * inv;
}

// ---------------- context: float4 per thread, 4 t-phases, 128-row chunks ----
__global__ void context_kernel(const float* __restrict__ enc,
                               const float* __restrict__ w,
                               float* __restrict__ c){
    __shared__ float sw[128];
    __shared__ float4 red[256];
    int tid = threadIdx.x;
    int b = blockIdx.z;
    int t0 = blockIdx.y * 128;
    if (tid < 128) sw[tid] = w[b * TT + t0 + tid];
    __syncthreads();

    int eq = tid & 63;          // float4 slot within 256-e block
    int g  = tid >> 6;          // t phase 0..3
    int e  = blockIdx.x * 256 + eq * 4;

    const float4* ep = (const float4*)(enc + ((size_t)(b * TT + t0 + g)) * ED + e);
    float4 acc = make_float4(0.f, 0.f, 0.f, 0.f);
#pragma unroll 8
    for (int j = 0; j < 32; ++j){
        float4 v = ep[(size_t)j * ED];     // row t0 + g + 4j
        float ww = sw[g + j * 4];
        acc.x = fmaf(v.x, ww, acc.x);
        acc.y = fmaf(v.y, ww, acc.y);
        acc.z = fmaf(v.z, ww, acc.z);
        acc.w = fmaf(v.w, ww, acc.w);
    }
    red[tid] = acc;
    __syncthreads();
    if (g == 0){
        float4 a0 = red[eq], a1 = red[eq + 64], a2 = red[eq + 128], a3 = red[eq + 192];
        float* dst = c + b * ED + e;
        atomicAdd(dst + 0, a0.x + a1.x + a2.x + a3.x);
        atomicAdd(dst + 1, a0.y + a1.y + a2.y + a3.y);
        atomicAdd(dst + 2, a0.z + a1.z + a2.z + a3.z);
        atomicAdd(dst + 3, a0.w + a1.w + a2.w + a3.w);
    }
}

// ---------------- launch ----------------
extern "C" void kernel_launch(void* const* d_in, const int* in_sizes, int n_in,
                              void* d_out, int out_size){
    const float*         encoder_out = (const float*)d_in[0];
    const unsigned char* mask        = (const unsigned char*)d_in[1];
    const float*         decoder_h   = (const float*)d_in[2];
    const float*         attn_state  = (const float*)d_in[3];
    const float*         W_enc       = (const float*)d_in[4];
    const float*         b_enc       = (const float*)d_in[5];
    const float*         W_dec       = (const float*)d_in[6];
    const float*         W_attn      = (const float*)d_in[7];
    const float*         W_conv      = (const float*)d_in[8];
    const float*         W_out       = (const float*)d_in[9];
    const float*         b_out       = (const float*)d_in[10];

    float* out_c = (float*)d_out;               // [B, ED]
    float* out_w = (float*)d_out + BQ * ED;     // [B, T]

    cudaFuncSetAttribute(mma_kernel, cudaFuncAttributeMaxDynamicSharedMemorySize, SMEM_REQ);

    prep_kernel<<<PREP_BLKS, 256>>>(attn_state, W_conv, W_enc, W_attn,
                                    decoder_h, W_dec, b_enc, out_c);
    mma_kernel<<<GRID_P, NTHREADS, SMEM_REQ>>>(encoder_out, W_out, b_out);
    softmax_kernel<<<BQ, 256>>>(mask, out_w);
    context_kernel<<<dim3(ED / 256, TT / 128, BQ), 256>>>(encoder_out, out_w, out_c);
}

// round 14
// speedup vs baseline: 1.0384x; 1.0384x over previous
#include <cuda_runtime.h>
#include <cuda_fp16.h>
#include <math.h>
#include <stdint.h>

// ---------------- problem constants ----------------
#define BQ 16
#define TT 2048
#define ED 1024
#define AD 512
#define DD 1024
#define CD 64
#define KSY 2
#define CK 15
#define KW 31
#define MM (BQ*TT)
#define KK 1088            // ED + CD concatenated K

// ---------------- GEMM tiling: BM128/BN256, BK=64 ----------------
#define BM 128
#define BN 256
#define BK 64
#define NKIT (KK/BK)       // 17
#define NENCKIT (ED/BK)    // 16
#define NTILES ((MM/BM)*(AD/BN))   // 512
#define STAGE_BYTES 49152  // A 16K + B 32K
#define SMEM_REQ (3*STAGE_BYTES)   // 144 KB
#define NTHREADS 512       // 16 warps: 2 (m) x 8 (n), warp tile 64x32
#define GRID_P 148

// ---------------- merged prep dispatch ----------------
#define CONV_BLKS (512*16)             // 8192
#define WS_BLKS AD                     // 512
#define DEC_BLKS 1024
#define INIT_BLKS 128
#define PREP_BLKS (CONV_BLKS + WS_BLKS + DEC_BLKS + INIT_BLKS)

// ---------------- scratch ----------------
__device__ __half g_Ahc[(size_t)MM*CD];   // conv features (fp16)
__device__ __half g_Bh[(size_t)AD*KK];
__device__ float  g_decproj[BQ*AD];
__device__ float  g_score[MM];

// ---------------- helpers ----------------
__device__ __forceinline__ uint32_t smem_u32(const void* p){
    uint32_t a;
    asm("{ .reg .u64 t; cvta.to.shared.u64 t, %1; cvt.u32.u64 %0, t; }" : "=r"(a) : "l"(p));
    return a;
}
__device__ __forceinline__ void cp16(uint32_t dst, const void* src){
    asm volatile("cp.async.cg.shared.global [%0], [%1], 16;" :: "r"(dst), "l"(src) : "memory");
}
// 128B rows, 8 x 16B granules, XOR swizzle
__device__ __forceinline__ uint32_t swz128(uint32_t r, uint32_t g){
    return r * 128u + ((g ^ (r & 7u)) << 4);
}
#define MMA16816(d, a, b) \
    asm volatile("mma.sync.aligned.m16n8k16.row.col.f32.f16.f16.f32 " \
        "{%0,%1,%2,%3}, {%4,%5,%6,%7}, {%8,%9}, {%0,%1,%2,%3};" \
        : "+f"((d)[0]), "+f"((d)[1]), "+f"((d)[2]), "+f"((d)[3]) \
        : "r"((a)[0]), "r"((a)[1]), "r"((a)[2]), "r"((a)[3]), \
          "r"((b)[0]), "r"((b)[1]))

// ---------------- merged prep: conv | w_split | dec | init ----------------
__global__ void prep_kernel(const float* __restrict__ state,
                            const float* __restrict__ Wc,
                            const float* __restrict__ We,
                            const float* __restrict__ Wa,
                            const float* __restrict__ h,
                            const float* __restrict__ Wd,
                            const float* __restrict__ be,
                            const float* __restrict__ b_out,
                            float* __restrict__ cctx){
    __shared__ float sW[CD * KSY * KW];
    int bid = blockIdx.x;
    int tid = threadIdx.x;

    if (bid < CONV_BLKS){
        for (int i = tid; i < CD * KSY * KW; i += 256) sW[i] = Wc[i];
        __syncthreads();

        int xb = bid & 511;
        int b  = bid >> 9;
        int c = tid & 63;
        int t = xb * 4 + (tid >> 6);

        const float* s0 = state + (b * KSY + 0) * TT;
        const float* s1 = state + (b * KSY + 1) * TT;
        const float* w0 = &sW[(c * KSY + 0) * KW];
        const float* w1 = &sW[(c * KSY + 1) * KW];

        float acc = 0.f;
#pragma unroll
        for (int hh = 0; hh < KW; ++hh){
            int tt = t + hh - CK;
            bool ok = (tt >= 0) && (tt < TT);
            float v0 = ok ? s0[tt] : 0.f;
            float v1 = ok ? s1[tt] : 0.f;
            acc = fmaf(v0, w0[hh], acc);
            acc = fmaf(v1, w1[hh], acc);
        }
        g_Ahc[(size_t)(b * TT + t) * CD + c] = __float2half_rn(acc);
    } else if (bid < CONV_BLKS + WS_BLKS){
        int n = bid - CONV_BLKS;
        for (int k = tid; k < KK; k += 256){
            float x = (k < ED) ? We[(size_t)n * ED + k] : Wa[n * CD + (k - ED)];
            g_Bh[(size_t)n * KK + k] = __float2half_rn(x);
        }
    } else if (bid < CONV_BLKS + WS_BLKS + DEC_BLKS){
        int bb = bid - CONV_BLKS - WS_BLKS;
        int wgid = (bb * 256 + tid) >> 5;
        int lane = tid & 31;
        int b = wgid >> 9;
        int a = wgid & (AD - 1);
        const float4* hv = (const float4*)(h + b * DD) + lane;
        const float4* wv = (const float4*)(Wd + (size_t)a * DD) + lane;
        float acc = 0.f;
#pragma unroll
        for (int k = 0; k < 8; ++k){
            float4 x = hv[k * 32], w = wv[k * 32];
            acc = fmaf(x.x, w.x, acc); acc = fmaf(x.y, w.y, acc);
            acc = fmaf(x.z, w.z, acc); acc = fmaf(x.w, w.w, acc);
        }
#pragma unroll
        for (int s = 16; s > 0; s >>= 1) acc += __shfl_xor_sync(~0u, acc, s);
        if (lane == 0) g_decproj[wgid] = acc + be[a];
    } else {
        int bb = bid - CONV_BLKS - WS_BLKS - DEC_BLKS;
        int i = bb * 256 + tid;
        if (i < MM) g_score[i] = b_out[0];
        if (i < BQ * ED) cctx[i] = 0.f;
    }
}

// ---------------- persistent fused GEMM, BK=64 ----------------
__global__ void __launch_bounds__(NTHREADS, 1)
mma_kernel(const float* __restrict__ enc, const float* __restrict__ Wout){
    extern __shared__ char smraw[];
    uint32_t sbase = smem_u32(smraw);
    int tid = threadIdx.x;
    int lane = tid & 31;
    int wid = tid >> 5;
    int warp_m = wid & 1;       // 0..1  -> 64 rows each
    int warp_n = wid >> 1;      // 0..7  -> 32 cols each

    // producer mapping: thread -> 2 granules (i = tid, tid+512) of 1024 A granules
    int rA0 = tid >> 3, gA0c = tid & 7;            // granule i=tid
    uint32_t stsOff0 = swz128((uint32_t)rA0, (uint32_t)gA0c);
    int rA1 = rA0 + 64;                            // granule i=tid+512
    uint32_t stsOff1 = swz128((uint32_t)rA1, (uint32_t)gA0c);

    // ldmatrix offset components: off = base[f] + ((kb*32 + g0) ^ x)
    uint32_t x16 = (uint32_t)(lane & 7) << 4;
    uint32_t gA0 = (uint32_t)(lane >> 4) << 4;          // A granule low bit
    uint32_t gB0 = (uint32_t)((lane >> 3) & 1) << 4;    // B granule low bit
    uint32_t baseA[4], baseB[2];
#pragma unroll
    for (int fm = 0; fm < 4; ++fm)
        baseA[fm] = (uint32_t)(warp_m * 64 + fm * 16 + (lane & 15)) * 128u;
#pragma unroll
    for (int fp = 0; fp < 2; ++fp)
        baseB[fp] = (uint32_t)(warp_n * 32 + fp * 16 + (((lane >> 4) & 1) * 8) + (lane & 7)) * 128u
                    + 16384u;

    for (int tile = blockIdx.x; tile < NTILES; tile += gridDim.x){
        int colBase = (tile & 1) * BN;
        int rowBase = (tile >> 1) * BM;

        __syncthreads();   // previous tile's stage reads all retired

        float acc[4][4][4];
#pragma unroll
        for (int fm = 0; fm < 4; ++fm)
#pragma unroll
            for (int fn = 0; fn < 4; ++fn)
#pragma unroll
                for (int q = 0; q < 4; ++q) acc[fm][fn][q] = 0.f;

        float4 av[4];
        auto ldgA = [&](int k0){
            const float* p0 = enc + (size_t)(rowBase + rA0) * ED + k0 + gA0c * 8;
            const float* p1 = enc + (size_t)(rowBase + rA1) * ED + k0 + gA0c * 8;
            av[0] = *(const float4*)p0; av[1] = *(const float4*)(p0 + 4);
            av[2] = *(const float4*)p1; av[3] = *(const float4*)(p1 + 4);
        };
        auto stsA = [&](uint32_t st){
            const float* xs = (const float*)av;
            uint32_t hq[8];
#pragma unroll
            for (int j = 0; j < 8; ++j){
                __half2 hh = __halves2half2(__float2half_rn(xs[2*j]),
                                            __float2half_rn(xs[2*j+1]));
                hq[j] = *(uint32_t*)&hh;
            }
            asm volatile("st.shared.v4.b32 [%0], {%1,%2,%3,%4};"
                :: "r"(st + stsOff0), "r"(hq[0]), "r"(hq[1]), "r"(hq[2]), "r"(hq[3]) : "memory");
            asm volatile("st.shared.v4.b32 [%0], {%1,%2,%3,%4};"
                :: "r"(st + stsOff1), "r"(hq[4]), "r"(hq[5]), "r"(hq[6]), "r"(hq[7]) : "memory");
        };
        auto cpB = [&](uint32_t st, int k0){
#pragma unroll
            for (int j = 0; j < 4; ++j){
                int i = tid + j * 512;
                int r = i >> 3, g = i & 7;
                cp16(st + 16384u + swz128((uint32_t)r, (uint32_t)g),
                     g_Bh + (size_t)(colBase + r) * KK + k0 + g * 8);
            }
        };
        auto cpConvA = [&](uint32_t st){
            cp16(st + stsOff0, g_Ahc + (size_t)(rowBase + rA0) * CD + gA0c * 8);
            cp16(st + stsOff1, g_Ahc + (size_t)(rowBase + rA1) * CD + gA0c * 8);
        };

        // ---- prologue ----
        ldgA(0);  stsA(sbase);                cpB(sbase, 0);
        asm volatile("cp.async.commit_group;" ::: "memory");
        ldgA(64); stsA(sbase + STAGE_BYTES);  cpB(sbase + STAGE_BYTES, 64);
        asm volatile("cp.async.commit_group;" ::: "memory");
        ldgA(128);

        // ---- mainloop: MMA first, then produce stage it+2 ----
        for (int it = 0; it < NKIT; ++it){
            asm volatile("cp.async.wait_group 1;" ::: "memory");
            __syncthreads();

            uint32_t st = sbase + (uint32_t)(it % 3) * STAGE_BYTES;
#pragma unroll
            for (int kb = 0; kb < 4; ++kb){
                uint32_t gsel = (uint32_t)(kb * 32);
                uint32_t b[4][2];
#pragma unroll
                for (int fp = 0; fp < 2; ++fp)
                    asm volatile("ldmatrix.sync.aligned.m8n8.x4.shared.b16 {%0,%1,%2,%3}, [%4];"
                        : "=r"(b[2*fp][0]), "=r"(b[2*fp][1]), "=r"(b[2*fp+1][0]), "=r"(b[2*fp+1][1])
                        : "r"(st + baseB[fp] + ((gsel + gB0) ^ x16)));
                uint32_t a[4][4];
#pragma unroll
                for (int fm = 0; fm < 4; ++fm)
                    asm volatile("ldmatrix.sync.aligned.m8n8.x4.shared.b16 {%0,%1,%2,%3}, [%4];"
                        : "=r"(a[fm][0]), "=r"(a[fm][1]), "=r"(a[fm][2]), "=r"(a[fm][3])
                        : "r"(st + baseA[fm] + ((gsel + gA0) ^ x16)));
#pragma unroll
                for (int fm = 0; fm < 4; ++fm)
#pragma unroll
                    for (int fn = 0; fn < 4; ++fn)
                        MMA16816(acc[fm][fn], a[fm], b[fn]);
            }

            // ---- produce stage it+2 while tensor pipe drains ----
            int nk = it + 2;
            uint32_t stn = sbase + (uint32_t)(nk % 3) * STAGE_BYTES;
            if (nk < NENCKIT){
                stsA(stn);
                cpB(stn, nk * BK);
                if (nk + 1 < NENCKIT) ldgA((nk + 1) * BK);
            } else if (nk == NENCKIT){
                cpConvA(stn);
                cpB(stn, nk * BK);
            }
            asm volatile("cp.async.commit_group;" ::: "memory");
        }

        // ---- epilogue: +decproj, tanh, dot W_out, reduce + atomic ----
        int b = rowBase >> 11;
        float wo[4][2], dp[4][2];
#pragma unroll
        for (int fn = 0; fn < 4; ++fn){
            int c0 = colBase + warp_n * 32 + fn * 8 + 2 * (lane & 3);
            wo[fn][0] = Wout[c0];               wo[fn][1] = Wout[c0 + 1];
            dp[fn][0] = g_decproj[b * AD + c0]; dp[fn][1] = g_decproj[b * AD + c0 + 1];
        }
        int g = lane >> 2;
#pragma unroll
        for (int fm = 0; fm < 4; ++fm){
            float s0 = 0.f, s1 = 0.f;
#pragma unroll
            for (int fn = 0; fn < 4; ++fn){
                s0 += tanhf(acc[fm][fn][0] + dp[fn][0]) * wo[fn][0];
                s0 += tanhf(acc[fm][fn][1] + dp[fn][1]) * wo[fn][1];
                s1 += tanhf(acc[fm][fn][2] + dp[fn][0]) * wo[fn][0];
                s1 += tanhf(acc[fm][fn][3] + dp[fn][1]) * wo[fn][1];
            }
            s0 += __shfl_xor_sync(~0u, s0, 1); s0 += __shfl_xor_sync(~0u, s0, 2);
            s1 += __shfl_xor_sync(~0u, s1, 1); s1 += __shfl_xor_sync(~0u, s1, 2);
            if ((lane & 3) == 0){
                int row = rowBase + warp_m * 64 + fm * 16 + g;
                atomicAdd(&g_score[row], s0);
                atomicAdd(&g_score[row + 8], s1);
            }
        }
    }
}

// ---------------- softmax over T per batch ----------------
__global__ void softmax_kernel(const unsigned char* __restrict__ mask,
                               float* __restrict__ wout){
    __shared__ float red[256];
    int b = blockIdx.x;
    int tid = threadIdx.x;

    float local[8];
    float mx = -INFINITY;
#pragma unroll
    for (int i = 0; i < 8; ++i){
        int t = i * 256 + tid;
        float v = g_score[b * TT + t];
        if (mask[b * TT + t]) v = -INFINITY;
        local[i] = v;
        mx = fmaxf(mx, v);
    }
    red[tid] = mx; __syncthreads();
    for (int s = 128; s > 0; s >>= 1){
        if (tid < s) red[tid] = fmaxf(red[tid], red[tid + s]);
        __syncthreads();
    }
    mx = red[0]; __syncthreads();

    float sum = 0.f;
#pragma unroll
    for (int i = 0; i < 8; ++i){
        local[i] = expf(2.f * (local[i] - mx));
        sum += local[i];
    }
    red[tid] = sum; __syncthreads();
    for (int s = 128; s > 0; s >>= 1){
        if (tid < s) red[tid] += red[tid + s];
        __syncthreads();
    }
    float inv = 1.f / red[0];
#pragma unroll
    for (int i = 0; i < 8; ++i)
        wout[b * TT + i * 256 + tid] = local[i] * inv;
}

// ---------------- context: float4 per thread, 4 t-phases, 128-row chunks ----
__global__ void context_kernel(const float* __restrict__ enc,
                               const float* __restrict__ w,
                               float* __restrict__ c){
    __shared__ float sw[128];
    __shared__ float4 red[256];
    int tid = threadIdx.x;
    int b = blockIdx.z;
    int t0 = blockIdx.y * 128;
    if (tid < 128) sw[tid] = w[b * TT + t0 + tid];
    __syncthreads();

    int eq = tid & 63;
    int g  = tid >> 6;
    int e  = blockIdx.x * 256 + eq * 4;

    const float4* ep = (const float4*)(enc + ((size_t)(b * TT + t0 + g)) * ED + e);
    float4 acc = make_float4(0.f, 0.f, 0.f, 0.f);
#pragma unroll 8
    for (int j = 0; j < 32; ++j){
        float4 v = ep[(size_t)j * ED];
        float ww = sw[g + j * 4];
        acc.x = fmaf(v.x, ww, acc.x);
        acc.y = fmaf(v.y, ww, acc.y);
        acc.z = fmaf(v.z, ww, acc.z);
        acc.w = fmaf(v.w, ww, acc.w);
    }
    red[tid] = acc;
    __syncthreads();
    if (g == 0){
        float4 a0 = red[eq], a1 = red[eq + 64], a2 = red[eq + 128], a3 = red[eq + 192];
        float* dst = c + b * ED + e;
        atomicAdd(dst + 0, a0.x + a1.x + a2.x + a3.x);
        atomicAdd(dst + 1, a0.y + a1.y + a2.y + a3.y);
        atomicAdd(dst + 2, a0.z + a1.z + a2.z + a3.z);
        atomicAdd(dst + 3, a0.w + a1.w + a2.w + a3.w);
    }
}

// ---------------- launch ----------------
extern "C" void kernel_launch(void* const* d_in, const int* in_sizes, int n_in,
                              void* d_out, int out_size){
    const float*         encoder_out = (const float*)d_in[0];
    const unsigned char* mask        = (const unsigned char*)d_in[1];
    const float*         decoder_h   = (const float*)d_in[2];
    const float*         attn_state  = (const float*)d_in[3];
    const float*         W_enc       = (const float*)d_in[4];
    const float*         b_enc       = (const float*)d_in[5];
    const float*         W_dec       = (const float*)d_in[6];
    const float*         W_attn      = (const float*)d_in[7];
    const float*         W_conv      = (const float*)d_in[8];
    const float*         W_out       = (const float*)d_in[9];
    const float*         b_out       = (const float*)d_in[10];

    float* out_c = (float*)d_out;               // [B, ED]
    float* out_w = (float*)d_out + BQ * ED;     // [B, T]

    cudaFuncSetAttribute(mma_kernel, cudaFuncAttributeMaxDynamicSharedMemorySize, SMEM_REQ);

    prep_kernel<<<PREP_BLKS, 256>>>(attn_state, W_conv, W_enc, W_attn,
                                    decoder_h, W_dec, b_enc, b_out, out_c);
    mma_kernel<<<GRID_P, NTHREADS, SMEM_REQ>>>(encoder_out, W_out);
    softmax_kernel<<<BQ, 256>>>(mask, out_w);
    context_kernel<<<dim3(ED / 256, TT / 128, BQ), 256>>>(encoder_out, out_w, out_c);
}